// round 14
// baseline (speedup 1.0000x reference)
#include <cuda_runtime.h>
#include <cstdint>

#define PS 32
#define NB 36
#define WPB 4                     // warps per block (128-thread CTAs)
#define PPW 4                     // patches per warp (8 lanes each)
#define THREADS (WPB * 32)

// Pad CTA smem footprint to ~15KB so residency caps at 14 CTAs/SM
// (228KB pool / (15360B + ~1KB reserve) = 14). 4096-CTA grid then runs
// 1.98 waves instead of 1.73 -> less wave-quantization loss.
#define HIST_BYTES (WPB * PPW * NB * 4)
#define SMEM_PAD   (15360 - HIST_BYTES)

// fp32 constants exactly as XLA materializes them
#define PI_F     3.14159274101257324219f   // (float)pi
#define TWOPI_F  6.28318548202514648438f   // (float)(2*pi)
#define INV_TWOPI (1.0f / TWOPI_F)         // compile-time RN reciprocal

// One pixel: exact reference fp32 op order (no fma contraction).
__device__ __forceinline__ void pixel(float lft, float rgt, float up, float dn,
                                      float g, float* __restrict__ h) {
    const float gx = __fmul_rn(0.5f, __fsub_rn(lft, rgt));
    const float gy = __fmul_rn(0.5f, __fsub_rn(up, dn));
    const float s2 = __fadd_rn(__fadd_rn(__fmul_rn(gx, gx), __fmul_rn(gy, gy)), 1e-10f);
    const float mag = __fmul_rn(sqrtf(s2), g);
    const float ori = atan2f(gy, gx);
    // o = (36*(ori+pi))/(2pi), correctly-rounded constant division (Markstein)
    const float num = __fmul_rn(36.0f, __fadd_rn(ori, PI_F));
    const float q0  = __fmul_rn(num, INV_TWOPI);
    const float e   = __fmaf_rn(-TWOPI_F, q0, num);
    const float o   = __fmaf_rn(e, INV_TWOPI, q0);
    const float bo = floorf(o);
    const float w  = __fmul_rn(__fsub_rn(1.0f, __fsub_rn(o, bo)), mag);
    int ib = (int)bo;
    if (ib >= NB) ib -= NB;       // only o==36 wraps (ori==+pi)
    atomicAdd(&h[ib], w);
}

__global__ __launch_bounds__(THREADS, 14)
void orient_kernel(const float* __restrict__ x,
                   const float* __restrict__ gk,
                   float* __restrict__ out, int B) {
    __shared__ float hist[WPB * PPW][NB];
    __shared__ char  smem_pad[SMEM_PAD];

    const int warp = threadIdx.x >> 5;
    const int lane = threadIdx.x & 31;
    const int p    = lane >> 3;          // patch within warp (0..3)
    const int s    = lane & 7;           // 4-col strip (cols 4s..4s+3)
    const int b    = (blockIdx.x * WPB + warp) * PPW + p;

    // Keep the pad alive: B is a runtime arg, this can never execute.
    if (B == -1) smem_pad[threadIdx.x] = (char)lane;

    if (b >= B) return;                  // warp-independent: no block syncs

    float* __restrict__ h = hist[warp * PPW + p];
    // Each warp zeros its own 4 histograms (144 floats) -> warp-local sync only.
    {
        float* hw = hist[warp * PPW];
        #pragma unroll
        for (int i = lane; i < PPW * NB; i += 32) hw[i] = 0.0f;
    }
    __syncwarp();

    const float4* px = reinterpret_cast<const float4*>(x + (size_t)b * (PS * PS)) + s;
    const float4* pg = reinterpret_cast<const float4*>(gk) + s;

    // Rolling float4 row buffer: upv=row r-1(clamped), cur=row r, dnv=row r+1(clamped)
    float4 cur = __ldg(px);              // row 0
    float4 dnv = __ldg(px + 8);          // row 1
    float4 upv = cur;                    // "row -1" = row 0 (replicate)

    #pragma unroll 4
    for (int r = 0; r < PS; r++) {
        const float4 g = __ldg(pg + r * 8);

        // Horizontal strip-edge neighbors. Patch border (s==0/s==7): replicate.
        const float li = __shfl_up_sync(0xffffffffu, cur.w, 1);
        const float ri = __shfl_down_sync(0xffffffffu, cur.x, 1);
        const float lft0 = (s == 0) ? cur.x : li;   // left of col 4s
        const float rgt3 = (s == 7) ? cur.w : ri;   // right of col 4s+3

        pixel(lft0,  cur.y, upv.x, dnv.x, g.x, h);
        pixel(cur.x, cur.z, upv.y, dnv.y, g.y, h);
        pixel(cur.y, cur.w, upv.z, dnv.z, g.z, h);
        pixel(cur.z, rgt3,  upv.w, dnv.w, g.w, h);

        // Rotate; load row r+2 (clamped) for the next iteration.
        upv = cur; cur = dnv;
        const int pr = (r + 2 < PS) ? (r + 2) : (PS - 1);
        dnv = __ldg(px + pr * 8);
    }
    __syncwarp();

    // Epilogue per 8-lane group: smooth (0.33,0.34,0.33) zero-padded,
    // first-max argmax, angle. Skipping /1024 is exactly argmax-equivalent.
    float bv = -1e30f;
    int bi = 0;
    #pragma unroll
    for (int k = 0; k < 5; k++) {
        const int i = s + k * 8;
        if (i < NB) {
            const float ctr = h[i];
            const float lft = (i > 0)      ? h[i - 1] : 0.0f;
            const float rgt = (i < NB - 1) ? h[i + 1] : 0.0f;
            const float sm = __fadd_rn(
                __fadd_rn(__fmul_rn(0.33f, lft), __fmul_rn(0.34f, ctr)),
                __fmul_rn(0.33f, rgt));
            if (sm > bv) { bv = sm; bi = i; }   // increasing i: '>' keeps first max
        }
    }
    #pragma unroll
    for (int off = 4; off > 0; off >>= 1) {     // reduce within 8-lane group
        const float ov = __shfl_xor_sync(0xffffffffu, bv, off);
        const int   oi = __shfl_xor_sync(0xffffffffu, bi, off);
        if (ov > bv || (ov == bv && oi < bi)) { bv = ov; bi = oi; }
    }
    if (s == 0) {
        // angle = -((2*pi*idx)/36 - pi), exact ref op order
        out[b] = -__fsub_rn(__fdiv_rn(__fmul_rn(TWOPI_F, (float)bi), 36.0f), PI_F);
    }
}

extern "C" void kernel_launch(void* const* d_in, const int* in_sizes, int n_in,
                              void* d_out, int out_size) {
    const float* x  = (const float*)d_in[0];
    const float* gk = (const float*)d_in[1];
    float* out = (float*)d_out;
    const int B = in_sizes[0] / (PS * PS);
    const int patches_per_block = WPB * PPW;
    const int grid = (B + patches_per_block - 1) / patches_per_block;
    orient_kernel<<<grid, THREADS>>>(x, gk, out, B);
}